// round 9
// baseline (speedup 1.0000x reference)
#include <cuda_runtime.h>
#include <cuda_bf16.h>
#include <cstdint>

// ---------------- problem constants ----------------
#define N_SPK 8192
#define M_UTT 10
#define D_EMB 128
#define CLAMP_MIN 1e-6f

// ---------------- gemm tiling ----------------
#define TM 128                       // rows per CTA
#define TN 128                       // cols per tile
#define COLS_PER_CTA 4096            // grid.x = 2 column halves
#define NTILES (COLS_PER_CTA / TN)   // 32
#define GTHREADS 256                 // 8 warps: warp tile 32(M) x 64(N)

#define ROW_BYTES 256                // 128 bf16
#define TILE_BYTES (128 * ROW_BYTES) // 32 KB
#define SMEM_TOTAL (3 * TILE_BYTES)  // A + B double buffer = 96 KB

// ---------------- device scratch ----------------
__device__ __align__(16) __nv_bfloat16 g_lhat[N_SPK * D_EMB];
__device__ __align__(16) __nv_bfloat16 g_chat[N_SPK * D_EMB];
__device__ float g_part[2][N_SPK];
__device__ float g_diag[N_SPK];

// ---------------- helpers ----------------
__device__ __forceinline__ uint32_t smem_u32(const void* p) {
    uint32_t a;
    asm("{ .reg .u64 t; cvta.to.shared.u64 t, %1; cvt.u32.u64 %0, t; }" : "=r"(a) : "l"(p));
    return a;
}
__device__ __forceinline__ void cp16(uint32_t dst, const void* src) {
    asm volatile("cp.async.cg.shared.global [%0], [%1], 16;" :: "r"(dst), "l"(src) : "memory");
}
#define CP_COMMIT() asm volatile("cp.async.commit_group;" ::: "memory")
#define CP_WAIT0()  asm volatile("cp.async.wait_group 0;" ::: "memory")

__device__ __forceinline__ void mma_bf16(float4& c, uint32_t a0, uint32_t a1,
                                         uint32_t a2, uint32_t a3,
                                         uint32_t b0, uint32_t b1) {
    asm volatile(
        "mma.sync.aligned.m16n8k16.row.col.f32.bf16.bf16.f32 "
        "{%0,%1,%2,%3}, {%4,%5,%6,%7}, {%8,%9}, {%0,%1,%2,%3};"
        : "+f"(c.x), "+f"(c.y), "+f"(c.z), "+f"(c.w)
        : "r"(a0), "r"(a1), "r"(a2), "r"(a3), "r"(b0), "r"(b1));
}

__device__ __forceinline__ float ex2f(float x) {
    float r; asm("ex2.approx.ftz.f32 %0, %1;" : "=f"(r) : "f"(x)); return r;
}
__device__ __forceinline__ float lg2f(float x) {
    float r; asm("lg2.approx.f32 %0, %1;" : "=f"(r) : "f"(x)); return r;
}
__device__ __forceinline__ uint32_t lds32(uint32_t a) {
    uint32_t v; asm volatile("ld.shared.b32 %0, [%1];" : "=r"(v) : "r"(a)); return v;
}

// ---------------------------------------------------------------------------
// Kernel 1: centroids + normalization + bf16 rounding. (DRAM-bound, ~10.5us)
// ---------------------------------------------------------------------------
__global__ void __launch_bounds__(256) prep_kernel(const float* __restrict__ x) {
    const int lane = threadIdx.x & 31;
    const int n = blockIdx.x * 8 + (threadIdx.x >> 5);
    const float4* xs = (const float4*)(x + (size_t)n * (M_UTT * D_EMB));

    float4 c = make_float4(0.f, 0.f, 0.f, 0.f);
    float4 l;
#pragma unroll
    for (int m = 0; m < M_UTT; m++) {
        float4 v = xs[m * 32 + lane];
        c.x += v.x; c.y += v.y; c.z += v.z; c.w += v.w;
        if (m == M_UTT - 1) l = v;
    }
    c.x *= 0.1f; c.y *= 0.1f; c.z *= 0.1f; c.w *= 0.1f;

    float sc = c.x * c.x + c.y * c.y + c.z * c.z + c.w * c.w;
    float sl = l.x * l.x + l.y * l.y + l.z * l.z + l.w * l.w;
#pragma unroll
    for (int o = 16; o; o >>= 1) {
        sc += __shfl_xor_sync(0xffffffffu, sc, o);
        sl += __shfl_xor_sync(0xffffffffu, sl, o);
    }
    const float rc = rsqrtf(sc), rl = rsqrtf(sl);

    __nv_bfloat162 c01 = __floats2bfloat162_rn(c.x * rc, c.y * rc);
    __nv_bfloat162 c23 = __floats2bfloat162_rn(c.z * rc, c.w * rc);
    __nv_bfloat162 l01 = __floats2bfloat162_rn(l.x * rl, l.y * rl);
    __nv_bfloat162 l23 = __floats2bfloat162_rn(l.z * rl, l.w * rl);

    uint2 cv, lv;
    cv.x = *(uint32_t*)&c01; cv.y = *(uint32_t*)&c23;
    lv.x = *(uint32_t*)&l01; lv.y = *(uint32_t*)&l23;
    ((uint2*)(g_chat + n * D_EMB))[lane] = cv;
    ((uint2*)(g_lhat + n * D_EMB))[lane] = lv;
}

// ---------------------------------------------------------------------------
// Kernel 2: mma.sync bf16 GEMM with epilogue software-pipelined into k-loop.
// Grid (2, 64), 256 threads. Two accumulator sets ping-pong; while the k-loop
// of tile t feeds the tensor pipe, the exp/row-sum of tile t-1 feeds MUFU/FMA.
// ---------------------------------------------------------------------------
__global__ void __launch_bounds__(GTHREADS, 1) gemm_lse_kernel(
    const float* __restrict__ wp, const float* __restrict__ bp) {
    extern __shared__ char smem[];
    const uint32_t sb = smem_u32(smem);

    const int tid = threadIdx.x;
    const int wid = tid >> 5, lane = tid & 31;
    const int warp_m = wid >> 1;          // 0..3 : 32-row stripe
    const int warp_n = wid & 1;           // 0..1 : 64-col stripe
    const int gid = lane >> 2;            // fragment group id (0..7)
    const int tid4 = lane & 3;

    const int h = blockIdx.x;
    const int rb = blockIdx.y;
    const int rowBase = rb * TM;
    const int colBase = h * COLS_PER_CTA;
    const int tdiag = ((rb >> 5) == h) ? (rb & 31) : -1;

    const float w = *wp, b = *bp;
    const float LOG2E = 1.44269504f;
    const float wl = w * LOG2E, bl = b * LOG2E;

    // ---- async-load A stripe + B tile 0 ----
    const float4* A4 = (const float4*)g_lhat;
    const float4* B4 = (const float4*)g_chat;
#pragma unroll
    for (int p = 0; p < 8; p++) {
        int idx = p * GTHREADS + tid;
        int r = idx >> 4, c = idx & 15;
        uint32_t doff = (uint32_t)(r * ROW_BYTES + ((c ^ (r & 7)) << 4));
        cp16(sb + doff, &A4[(rowBase + r) * 16 + c]);
        cp16(sb + TILE_BYTES + doff, &B4[(colBase + r) * 16 + c]);
    }
    CP_COMMIT();
    CP_WAIT0();
    __syncthreads();

    const uint32_t aRow = sb + (uint32_t)((warp_m * 32 + gid) * ROW_BYTES);
    const uint32_t bRel = (uint32_t)((warp_n * 64 + gid) * ROW_BYTES);
    const uint32_t cOff = (uint32_t)(tid4 * 4);

    float4 accA[2][8], accB[2][8];
    float rs[4] = {0.f, 0.f, 0.f, 0.f};

    // Drain one 8-value chunk (column-group ks) of a finished accumulator set.
    auto drainChunk = [&](float4 (&accP)[2][8], int ks, bool isDiag) {
#pragma unroll
        for (int i = 0; i < 2; i++) {
            const int r0 = warp_m * 32 + i * 16 + gid;
            const int c0 = warp_n * 64 + ks * 8 + tid4 * 2;
            float4 v = accP[i][ks];
            float e0 = fmaxf(v.x, CLAMP_MIN);
            float e1 = fmaxf(v.y, CLAMP_MIN);
            float e2 = fmaxf(v.z, CLAMP_MIN);
            float e3 = fmaxf(v.w, CLAMP_MIN);
            rs[i * 2 + 0] += ex2f(fmaf(e0, wl, bl)) + ex2f(fmaf(e1, wl, bl));
            rs[i * 2 + 1] += ex2f(fmaf(e2, wl, bl)) + ex2f(fmaf(e3, wl, bl));
            if (isDiag) {
                if (r0 == c0)         g_diag[rowBase + r0] = fmaf(e0, w, b);
                if (r0 == c0 + 1)     g_diag[rowBase + r0] = fmaf(e1, w, b);
                if (r0 + 8 == c0)     g_diag[rowBase + r0 + 8] = fmaf(e2, w, b);
                if (r0 + 8 == c0 + 1) g_diag[rowBase + r0 + 8] = fmaf(e3, w, b);
            }
        }
    };

    // One tile phase: prefetch t+1, k-loop for tile t into accC, interleaved
    // drain of tile t-1 from accP (if doDrain).
    auto phase = [&](float4 (&accC)[2][8], float4 (&accP)[2][8], int t, bool doDrain) {
        const uint32_t bBuf = sb + TILE_BYTES * (1 + (t & 1));
        const bool doPrefetch = (t + 1 < NTILES);
        if (doPrefetch) {
            const int nb = t + 1;
#pragma unroll
            for (int p = 0; p < 8; p++) {
                int idx = p * GTHREADS + tid;
                int r = idx >> 4, c = idx & 15;
                uint32_t doff = (uint32_t)(r * ROW_BYTES + ((c ^ (r & 7)) << 4));
                cp16(sb + TILE_BYTES * (1 + (nb & 1)) + doff,
                     &B4[(colBase + nb * TN + r) * 16 + c]);
            }
            CP_COMMIT();
        }

#pragma unroll
        for (int i = 0; i < 2; i++)
#pragma unroll
            for (int j = 0; j < 8; j++) accC[i][j] = make_float4(0.f, 0.f, 0.f, 0.f);

        const bool isDiag = doDrain && (t - 1 == tdiag);
#pragma unroll
        for (int ks = 0; ks < 8; ks++) {
            const uint32_t off0 = (uint32_t)(((2 * ks) ^ gid) << 4) + cOff;
            const uint32_t off1 = (uint32_t)(((2 * ks + 1) ^ gid) << 4) + cOff;

            uint32_t a[2][4];
#pragma unroll
            for (int i = 0; i < 2; i++) {
                const uint32_t base = aRow + (uint32_t)(i * 16 * ROW_BYTES);
                a[i][0] = lds32(base + off0);
                a[i][1] = lds32(base + 8 * ROW_BYTES + off0);
                a[i][2] = lds32(base + off1);
                a[i][3] = lds32(base + 8 * ROW_BYTES + off1);
            }
            uint32_t bf[8][2];
#pragma unroll
            for (int j = 0; j < 8; j++) {
                const uint32_t base = bBuf + bRel + (uint32_t)(j * 8 * ROW_BYTES);
                bf[j][0] = lds32(base + off0);
                bf[j][1] = lds32(base + off1);
            }
            if (doDrain) drainChunk(accP, ks, isDiag);   // fills MUFU/FMA pipes
#pragma unroll
            for (int i = 0; i < 2; i++)
#pragma unroll
                for (int j = 0; j < 8; j++)
                    mma_bf16(accC[i][j], a[i][0], a[i][1], a[i][2], a[i][3],
                             bf[j][0], bf[j][1]);
        }

        if (doPrefetch) CP_WAIT0();
        __syncthreads();
    };

    // tile 0: fill accA, nothing to drain
    phase(accA, accB, 0, false);
    // tiles 1..31, unrolled by 2 for register ping-pong
    for (int tt = 1; tt < NTILES; tt += 2) {
        phase(accB, accA, tt, true);          // k-loop tile tt, drain tile tt-1
        if (tt + 1 < NTILES)
            phase(accA, accB, tt + 1, true);  // k-loop tile tt+1, drain tile tt
    }
    // drain the last tile (NTILES-1 lives in accB since NTILES is even)
    {
        const bool isDiag = (NTILES - 1 == tdiag);
#pragma unroll
        for (int ks = 0; ks < 8; ks++) drainChunk(accB, ks, isDiag);
    }

    // ---- reduce rs across tid4 lanes, then across the 2 N-warps ----
#pragma unroll
    for (int q = 0; q < 4; q++) {
        rs[q] += __shfl_xor_sync(0xffffffffu, rs[q], 1);
        rs[q] += __shfl_xor_sync(0xffffffffu, rs[q], 2);
    }
    float* red = (float*)smem;   // reuse A smem
    if (warp_n == 0 && tid4 == 0) {
#pragma unroll
        for (int i = 0; i < 2; i++) {
            red[warp_m * 32 + i * 16 + gid] = rs[i * 2 + 0];
            red[warp_m * 32 + i * 16 + 8 + gid] = rs[i * 2 + 1];
        }
    }
    __syncthreads();
    if (warp_n == 1 && tid4 == 0) {
#pragma unroll
        for (int i = 0; i < 2; i++) {
            int r = warp_m * 32 + i * 16 + gid;
            g_part[h][rowBase + r] = red[r] + rs[i * 2 + 0];
            g_part[h][rowBase + r + 8] = red[r + 8] + rs[i * 2 + 1];
        }
    }
}

// ---------------------------------------------------------------------------
// Kernel 3: loss = mean(log(rowsum) - diag_logit)
// ---------------------------------------------------------------------------
__global__ void __launch_bounds__(1024) final_kernel(float* __restrict__ out) {
    const int tid = threadIdx.x;
    const float LN2 = 0.69314718056f;
    float s = 0.f;
#pragma unroll
    for (int i = 0; i < 8; i++) {
        int r = tid + i * 1024;
        float sum = g_part[0][r] + g_part[1][r];
        s += lg2f(sum) * LN2 - g_diag[r];
    }
#pragma unroll
    for (int o = 16; o; o >>= 1) s += __shfl_xor_sync(0xffffffffu, s, o);
    __shared__ float sred[32];
    const int wid = tid >> 5, lane = tid & 31;
    if (lane == 0) sred[wid] = s;
    __syncthreads();
    if (wid == 0) {
        float v = sred[lane];
#pragma unroll
        for (int o = 16; o; o >>= 1) v += __shfl_xor_sync(0xffffffffu, v, o);
        if (lane == 0) out[0] = v * (1.0f / (float)N_SPK);
    }
}

extern "C" void kernel_launch(void* const* d_in, const int* in_sizes, int n_in,
                              void* d_out, int out_size) {
    const float* x = (const float*)d_in[0];
    const float* w = (const float*)d_in[1];
    const float* b = (const float*)d_in[2];
    float* out = (float*)d_out;
    (void)in_sizes; (void)n_in; (void)out_size;

    cudaFuncSetAttribute(gemm_lse_kernel,
                         cudaFuncAttributeMaxDynamicSharedMemorySize, SMEM_TOTAL);

    prep_kernel<<<N_SPK / 8, 256>>>(x);
    gemm_lse_kernel<<<dim3(2, 64), GTHREADS, SMEM_TOTAL>>>(w, b);
    final_kernel<<<1, 1024>>>(out);
}

// round 10
// speedup vs baseline: 1.1255x; 1.1255x over previous
#include <cuda_runtime.h>
#include <cuda_bf16.h>
#include <cstdint>

// ---------------- problem constants ----------------
#define N_SPK 8192
#define M_UTT 10
#define D_EMB 128
#define CLAMP_MIN 1e-6f

// ---------------- gemm tiling ----------------
#define TM 128                        // rows per CTA
#define TN 256                        // cols per tile
#define COLS_PER_CTA 4096             // grid.x = 2 column halves
#define NTILES (COLS_PER_CTA / TN)    // 16
#define GTHREADS 256                  // 8 warps: 2(M) x 4(N), warp tile 64x64

#define ROW_BYTES 256                 // 128 bf16
#define A_BYTES   (128 * ROW_BYTES)   // 32 KB
#define B_BYTES   (256 * ROW_BYTES)   // 64 KB per buffer
#define SMEM_TOTAL (A_BYTES + 2 * B_BYTES)   // 160 KB

// ---------------- device scratch ----------------
__device__ __align__(16) __nv_bfloat16 g_lhat[N_SPK * D_EMB];
__device__ __align__(16) __nv_bfloat16 g_chat[N_SPK * D_EMB];
__device__ float g_part[2][N_SPK];
__device__ float g_diag[N_SPK];

// ---------------- helpers ----------------
__device__ __forceinline__ uint32_t smem_u32(const void* p) {
    uint32_t a;
    asm("{ .reg .u64 t; cvta.to.shared.u64 t, %1; cvt.u32.u64 %0, t; }" : "=r"(a) : "l"(p));
    return a;
}
__device__ __forceinline__ void cp16(uint32_t dst, const void* src) {
    asm volatile("cp.async.cg.shared.global [%0], [%1], 16;" :: "r"(dst), "l"(src) : "memory");
}
#define CP_COMMIT() asm volatile("cp.async.commit_group;" ::: "memory")
#define CP_WAIT0()  asm volatile("cp.async.wait_group 0;" ::: "memory")

#define LDMX4(r0, r1, r2, r3, addr)                                            \
    asm volatile("ldmatrix.sync.aligned.m8n8.x4.shared.b16 {%0,%1,%2,%3}, [%4];" \
                 : "=r"(r0), "=r"(r1), "=r"(r2), "=r"(r3) : "r"(addr))

__device__ __forceinline__ void mma_bf16(float4& c, uint32_t a0, uint32_t a1,
                                         uint32_t a2, uint32_t a3,
                                         uint32_t b0, uint32_t b1) {
    asm volatile(
        "mma.sync.aligned.m16n8k16.row.col.f32.bf16.bf16.f32 "
        "{%0,%1,%2,%3}, {%4,%5,%6,%7}, {%8,%9}, {%0,%1,%2,%3};"
        : "+f"(c.x), "+f"(c.y), "+f"(c.z), "+f"(c.w)
        : "r"(a0), "r"(a1), "r"(a2), "r"(a3), "r"(b0), "r"(b1));
}

__device__ __forceinline__ float ex2f(float x) {
    float r; asm("ex2.approx.ftz.f32 %0, %1;" : "=f"(r) : "f"(x)); return r;
}
__device__ __forceinline__ float lg2f(float x) {
    float r; asm("lg2.approx.f32 %0, %1;" : "=f"(r) : "f"(x)); return r;
}

// ---------------------------------------------------------------------------
// Kernel 1: centroids + normalization + bf16 rounding. (DRAM-bound, ~10.5us)
// ---------------------------------------------------------------------------
__global__ void __launch_bounds__(256) prep_kernel(const float* __restrict__ x) {
    const int lane = threadIdx.x & 31;
    const int n = blockIdx.x * 8 + (threadIdx.x >> 5);
    const float4* xs = (const float4*)(x + (size_t)n * (M_UTT * D_EMB));

    float4 c = make_float4(0.f, 0.f, 0.f, 0.f);
    float4 l;
#pragma unroll
    for (int m = 0; m < M_UTT; m++) {
        float4 v = xs[m * 32 + lane];
        c.x += v.x; c.y += v.y; c.z += v.z; c.w += v.w;
        if (m == M_UTT - 1) l = v;
    }
    c.x *= 0.1f; c.y *= 0.1f; c.z *= 0.1f; c.w *= 0.1f;

    float sc = c.x * c.x + c.y * c.y + c.z * c.z + c.w * c.w;
    float sl = l.x * l.x + l.y * l.y + l.z * l.z + l.w * l.w;
#pragma unroll
    for (int o = 16; o; o >>= 1) {
        sc += __shfl_xor_sync(0xffffffffu, sc, o);
        sl += __shfl_xor_sync(0xffffffffu, sl, o);
    }
    const float rc = rsqrtf(sc), rl = rsqrtf(sl);

    __nv_bfloat162 c01 = __floats2bfloat162_rn(c.x * rc, c.y * rc);
    __nv_bfloat162 c23 = __floats2bfloat162_rn(c.z * rc, c.w * rc);
    __nv_bfloat162 l01 = __floats2bfloat162_rn(l.x * rl, l.y * rl);
    __nv_bfloat162 l23 = __floats2bfloat162_rn(l.z * rl, l.w * rl);

    uint2 cv, lv;
    cv.x = *(uint32_t*)&c01; cv.y = *(uint32_t*)&c23;
    lv.x = *(uint32_t*)&l01; lv.y = *(uint32_t*)&l23;
    ((uint2*)(g_chat + n * D_EMB))[lane] = cv;
    ((uint2*)(g_lhat + n * D_EMB))[lane] = lv;
}

// ---------------------------------------------------------------------------
// Kernel 2: mma.sync bf16 GEMM, warp tile 64x64, ldmatrix fragment loads.
// Grid (2, 64), 256 threads. Smem: A 32KB + B double buffer 2x64KB.
// Swizzle: 16B chunk c of row r stored at c ^ (r & 7).
// ---------------------------------------------------------------------------
__global__ void __launch_bounds__(GTHREADS, 1) gemm_lse_kernel(
    const float* __restrict__ wp, const float* __restrict__ bp) {
    extern __shared__ char smem[];
    const uint32_t sb = smem_u32(smem);

    const int tid = threadIdx.x;
    const int wid = tid >> 5, lane = tid & 31;
    const int warp_m = wid >> 2;          // 0..1 : 64-row stripe
    const int warp_n = wid & 3;           // 0..3 : 64-col stripe
    const int gid = lane >> 2;            // 0..7
    const int tid4 = lane & 3;

    const int h = blockIdx.x;
    const int rb = blockIdx.y;
    const int rowBase = rb * TM;
    const int colBase = h * COLS_PER_CTA;
    const int tdiag = ((rb >> 5) == h) ? ((rb - h * 32) >> 1) : -1;
    const int dOff = (rb & 1) * 128;      // local col offset of diag block

    const float w = *wp, b = *bp;
    const float LOG2E = 1.44269504f;
    const float wl = w * LOG2E, bl = b * LOG2E;

    // ---- async-load A stripe (8 chunks/thr) + B tile 0 (16 chunks/thr) ----
    const float4* A4 = (const float4*)g_lhat;
    const float4* B4 = (const float4*)g_chat;
#pragma unroll
    for (int p = 0; p < 8; p++) {
        int idx = p * GTHREADS + tid;
        int r = idx >> 4, c = idx & 15;
        cp16(sb + (uint32_t)(r * ROW_BYTES + ((c ^ (r & 7)) << 4)),
             &A4[(rowBase + r) * 16 + c]);
    }
#pragma unroll
    for (int p = 0; p < 16; p++) {
        int idx = p * GTHREADS + tid;
        int r = idx >> 4, c = idx & 15;
        cp16(sb + A_BYTES + (uint32_t)(r * ROW_BYTES + ((c ^ (r & 7)) << 4)),
             &B4[(colBase + r) * 16 + c]);
    }
    CP_COMMIT();
    CP_WAIT0();
    __syncthreads();

    // ---- ldmatrix lane-address precompute ----
    // A frag i (m16k16): lanes 0-15 -> rows +0..15 (k-chunk 2ks), 16-31 -> same rows (2ks+1)
    uint32_t aBase[4]; uint32_t aSw[4];
    const int aK = lane >> 4;
#pragma unroll
    for (int i = 0; i < 4; i++) {
        int row = warp_m * 64 + i * 16 + (lane & 15);
        aBase[i] = sb + (uint32_t)(row * ROW_BYTES);
        aSw[i] = (uint32_t)(row & 7);
    }
    // B pair j2 (two n8k16 frags): lanes 0-7 n0-7/kc0, 8-15 n0-7/kc1, 16-23 n8-15/kc0, 24-31 n8-15/kc1
    uint32_t bBase[4]; uint32_t bSw[4];
    const int bK = (lane >> 3) & 1;
    const int nLoc = ((lane >> 4) << 3) + (lane & 7);
#pragma unroll
    for (int j2 = 0; j2 < 4; j2++) {
        int row = warp_n * 64 + j2 * 16 + nLoc;
        bBase[j2] = (uint32_t)(row * ROW_BYTES);
        bSw[j2] = (uint32_t)(row & 7);
    }

    float4 acc[4][8];
    float rs[8];
#pragma unroll
    for (int q = 0; q < 8; q++) rs[q] = 0.f;

    for (int t = 0; t < NTILES; t++) {
        const uint32_t bBuf = sb + A_BYTES + (uint32_t)((t & 1) * B_BYTES);

        // prefetch next B tile into the other buffer
        if (t + 1 < NTILES) {
            const int nb = t + 1;
            const uint32_t nBuf = sb + A_BYTES + (uint32_t)((nb & 1) * B_BYTES);
#pragma unroll
            for (int p = 0; p < 16; p++) {
                int idx = p * GTHREADS + tid;
                int r = idx >> 4, c = idx & 15;
                cp16(nBuf + (uint32_t)(r * ROW_BYTES + ((c ^ (r & 7)) << 4)),
                     &B4[(colBase + nb * TN + r) * 16 + c]);
            }
            CP_COMMIT();
        }

#pragma unroll
        for (int i = 0; i < 4; i++)
#pragma unroll
            for (int j = 0; j < 8; j++) acc[i][j] = make_float4(0.f, 0.f, 0.f, 0.f);

        // ---- k-loop: 8 steps of k=16 ----
#pragma unroll
        for (int ks = 0; ks < 8; ks++) {
            uint32_t a[4][4], bq[4][4];
#pragma unroll
            for (int i = 0; i < 4; i++) {
                uint32_t addr = aBase[i] + ((((uint32_t)(2 * ks + aK)) ^ aSw[i]) << 4);
                LDMX4(a[i][0], a[i][1], a[i][2], a[i][3], addr);
            }
#pragma unroll
            for (int j2 = 0; j2 < 4; j2++) {
                uint32_t addr = bBuf + bBase[j2] + ((((uint32_t)(2 * ks + bK)) ^ bSw[j2]) << 4);
                LDMX4(bq[j2][0], bq[j2][1], bq[j2][2], bq[j2][3], addr);
            }
#pragma unroll
            for (int i = 0; i < 4; i++)
#pragma unroll
                for (int j = 0; j < 8; j++)
                    mma_bf16(acc[i][j], a[i][0], a[i][1], a[i][2], a[i][3],
                             bq[j >> 1][(j & 1) * 2], bq[j >> 1][(j & 1) * 2 + 1]);
        }

        // ---- epilogue: exp from registers ----
        const bool isDiag = (t == tdiag);
#pragma unroll
        for (int i = 0; i < 4; i++) {
            const int r0 = warp_m * 64 + i * 16 + gid;
#pragma unroll
            for (int j = 0; j < 8; j++) {
                const int c0 = warp_n * 64 + j * 8 + tid4 * 2;
                float4 v = acc[i][j];
                float e0 = fmaxf(v.x, CLAMP_MIN);
                float e1 = fmaxf(v.y, CLAMP_MIN);
                float e2 = fmaxf(v.z, CLAMP_MIN);
                float e3 = fmaxf(v.w, CLAMP_MIN);
                rs[i * 2 + 0] += ex2f(fmaf(e0, wl, bl)) + ex2f(fmaf(e1, wl, bl));
                rs[i * 2 + 1] += ex2f(fmaf(e2, wl, bl)) + ex2f(fmaf(e3, wl, bl));
                if (isDiag) {
                    const int c = c0 - dOff;
                    if (r0 == c)         g_diag[rowBase + r0] = fmaf(e0, w, b);
                    if (r0 == c + 1)     g_diag[rowBase + r0] = fmaf(e1, w, b);
                    if (r0 + 8 == c)     g_diag[rowBase + r0 + 8] = fmaf(e2, w, b);
                    if (r0 + 8 == c + 1) g_diag[rowBase + r0 + 8] = fmaf(e3, w, b);
                }
            }
        }

        if (t + 1 < NTILES) CP_WAIT0();
        __syncthreads();
    }

    // ---- reduce rs across tid4 lanes (same rows), then across the 4 N-warps ----
#pragma unroll
    for (int q = 0; q < 8; q++) {
        rs[q] += __shfl_xor_sync(0xffffffffu, rs[q], 1);
        rs[q] += __shfl_xor_sync(0xffffffffu, rs[q], 2);
    }
    float* red = (float*)smem;   // 4 x 128 floats, reuse A smem
    if (tid4 == 0) {
#pragma unroll
        for (int i = 0; i < 4; i++) {
            int r = warp_m * 64 + i * 16 + gid;
            red[warp_n * 128 + r] = rs[i * 2 + 0];
            red[warp_n * 128 + r + 8] = rs[i * 2 + 1];
        }
    }
    __syncthreads();
    if (tid < 128) {
        g_part[h][rowBase + tid] =
            red[tid] + red[128 + tid] + red[256 + tid] + red[384 + tid];
    }
}

// ---------------------------------------------------------------------------
// Kernel 3: loss = mean(log(rowsum) - diag_logit)
// ---------------------------------------------------------------------------
__global__ void __launch_bounds__(1024) final_kernel(float* __restrict__ out) {
    const int tid = threadIdx.x;
    const float LN2 = 0.69314718056f;
    float s = 0.f;
#pragma unroll
    for (int i = 0; i < 8; i++) {
        int r = tid + i * 1024;
        float sum = g_part[0][r] + g_part[1][r];
        s += lg2f(sum) * LN2 - g_diag[r];
    }
#pragma unroll
    for (int o = 16; o; o >>= 1) s += __shfl_xor_sync(0xffffffffu, s, o);
    __shared__ float sred[32];
    const int wid = tid >> 5, lane = tid & 31;
    if (lane == 0) sred[wid] = s;
    __syncthreads();
    if (wid == 0) {
        float v = sred[lane];
#pragma unroll
        for (int o = 16; o; o >>= 1) v += __shfl_xor_sync(0xffffffffu, v, o);
        if (lane == 0) out[0] = v * (1.0f / (float)N_SPK);
    }
}

extern "C" void kernel_launch(void* const* d_in, const int* in_sizes, int n_in,
                              void* d_out, int out_size) {
    const float* x = (const float*)d_in[0];
    const float* w = (const float*)d_in[1];
    const float* b = (const float*)d_in[2];
    float* out = (float*)d_out;
    (void)in_sizes; (void)n_in; (void)out_size;

    cudaFuncSetAttribute(gemm_lse_kernel,
                         cudaFuncAttributeMaxDynamicSharedMemorySize, SMEM_TOTAL);

    prep_kernel<<<N_SPK / 8, 256>>>(x);
    gemm_lse_kernel<<<dim3(2, 64), GTHREADS, SMEM_TOTAL>>>(w, b);
    final_kernel<<<1, 1024>>>(out);
}